// round 1
// baseline (speedup 1.0000x reference)
#include <cuda_runtime.h>

// OLCNN: per-element tiny grouped network, fully fused.
//   x (B,81) -> 9 patches of 9 px -> conv 9x9 sigmoid -> 81
//   -> hidden 9x3 sigmoid -> 27 -> middle 3x4 sigmoid -> 12 -> 4 logits
//
// Design:
//  - block = 256 threads, 256 elements/block
//  - stage x into smem transposed [k][e] (stride 257 -> conflict-free compute reads)
//  - weights in __constant__ (LDCU uniform path on sm_103a)
//  - fully unrolled; h[27]/m[12] live in registers
//  - float4 coalesced in (global->smem) and out (logits)

#define NTHREADS 256
#define ELEMS    256
#define ESTRIDE  257   // 257 % 32 == 1 -> bank = (k + e) % 32

__constant__ float cWc[729];
__constant__ float cbc[81];
__constant__ float cWh[243];
__constant__ float cbh[27];
__constant__ float cWm[108];
__constant__ float cbm[12];
__constant__ float cWo[16];
__constant__ float cbo[4];

__device__ __forceinline__ float sigm(float v) {
    // 1 / (1 + e^-v): EX2 + RCP (fast MUFU path)
    return __fdividef(1.0f, 1.0f + __expf(-v));
}

extern __shared__ float s_x[];   // [81][ESTRIDE]

__global__ __launch_bounds__(NTHREADS, 2)
void olcnn_kernel(const float* __restrict__ x, float* __restrict__ out) {
    const int tid = threadIdx.x;
    const long long blk = blockIdx.x;

    // ---- Stage 1: coalesced load of 256 elements (20736 floats) into smem, transposed ----
    const float4* __restrict__ x4 =
        reinterpret_cast<const float4*>(x + blk * (long long)(ELEMS * 81));
    for (int i = tid; i < (ELEMS * 81) / 4; i += NTHREADS) {
        float4 v = x4[i];
        int f = i * 4;
        float vv[4] = {v.x, v.y, v.z, v.w};
        #pragma unroll
        for (int j = 0; j < 4; j++) {
            int idx = f + j;
            int e = idx / 81;          // const-div -> mul/shift
            int k = idx - e * 81;
            s_x[k * ESTRIDE + e] = vv[j];
        }
    }
    __syncthreads();

    // ---- Stage 2: per-thread network (element e = tid) ----
    float h[27];

    #pragma unroll
    for (int g = 0; g < 9; g++) {
        const int gr = g / 3, gc = g % 3;

        // 9 patch pixels (conflict-free smem reads: consecutive lanes -> consecutive banks)
        float px[9];
        #pragma unroll
        for (int p = 0; p < 9; p++) {
            const int pr = p / 3, pc = p % 3;
            const int k = (3 * gr + pr) * 9 + (3 * gc + pc);
            px[p] = s_x[k * ESTRIDE + tid];
        }

        // conv layer: 9 kernels over this patch
        float f[9];
        #pragma unroll
        for (int k = 0; k < 9; k++) {
            float acc = cbc[g * 9 + k];
            #pragma unroll
            for (int p = 0; p < 9; p++)
                acc = fmaf(px[p], cWc[(g * 9 + k) * 9 + p], acc);
            f[k] = sigm(acc);
        }

        // hidden layer: 3 neurons over the 9 conv outputs of this group
        #pragma unroll
        for (int n = 0; n < 3; n++) {
            float acc = cbh[g * 3 + n];
            #pragma unroll
            for (int k = 0; k < 9; k++)
                acc = fmaf(f[k], cWh[(g * 3 + n) * 9 + k], acc);
            h[g * 3 + n] = sigm(acc);
        }
    }

    // middle layer: 3 groups x 4 neurons over 9 hidden values each
    float m[12];
    #pragma unroll
    for (int G = 0; G < 3; G++) {
        #pragma unroll
        for (int n = 0; n < 4; n++) {
            float acc = cbm[G * 4 + n];
            #pragma unroll
            for (int p = 0; p < 9; p++)
                acc = fmaf(h[G * 9 + p], cWm[(G * 4 + n) * 9 + p], acc);
            m[G * 4 + n] = sigm(acc);
        }
    }

    // output layer: class c reads middle group c % 3
    float lo[4];
    #pragma unroll
    for (int c = 0; c < 4; c++) {
        const int G = c % 3;
        float acc = cbo[c];
        #pragma unroll
        for (int p = 0; p < 4; p++)
            acc = fmaf(m[G * 4 + p], cWo[c * 4 + p], acc);
        lo[c] = acc;
    }

    float4* __restrict__ o4 = reinterpret_cast<float4*>(out);
    o4[blk * ELEMS + tid] = make_float4(lo[0], lo[1], lo[2], lo[3]);
}

extern "C" void kernel_launch(void* const* d_in, const int* in_sizes, int n_in,
                              void* d_out, int out_size) {
    const float* x = (const float*)d_in[0];

    // weights -> constant bank (async D2D memcpy nodes; graph-capturable)
    cudaMemcpyToSymbolAsync(cWc, d_in[1], 729 * sizeof(float), 0, cudaMemcpyDeviceToDevice, 0);
    cudaMemcpyToSymbolAsync(cbc, d_in[2],  81 * sizeof(float), 0, cudaMemcpyDeviceToDevice, 0);
    cudaMemcpyToSymbolAsync(cWh, d_in[3], 243 * sizeof(float), 0, cudaMemcpyDeviceToDevice, 0);
    cudaMemcpyToSymbolAsync(cbh, d_in[4],  27 * sizeof(float), 0, cudaMemcpyDeviceToDevice, 0);
    cudaMemcpyToSymbolAsync(cWm, d_in[5], 108 * sizeof(float), 0, cudaMemcpyDeviceToDevice, 0);
    cudaMemcpyToSymbolAsync(cbm, d_in[6],  12 * sizeof(float), 0, cudaMemcpyDeviceToDevice, 0);
    cudaMemcpyToSymbolAsync(cWo, d_in[7],  16 * sizeof(float), 0, cudaMemcpyDeviceToDevice, 0);
    cudaMemcpyToSymbolAsync(cbo, d_in[8],   4 * sizeof(float), 0, cudaMemcpyDeviceToDevice, 0);

    const int B = in_sizes[0] / 81;          // 524288
    const int nblocks = B / ELEMS;           // 2048

    const size_t smem = 81 * ESTRIDE * sizeof(float);  // 83268 B
    cudaFuncSetAttribute(olcnn_kernel, cudaFuncAttributeMaxDynamicSharedMemorySize, (int)smem);

    olcnn_kernel<<<nblocks, NTHREADS, smem>>>(x, (float*)d_out);
}